// round 9
// baseline (speedup 1.0000x reference)
#include <cuda_runtime.h>
#include <cuda_bf16.h>
#include <cstdint>

#define N_NODES 50000
#define N_EDGES 400000
#define E_TOT   (N_EDGES + N_NODES)
#define G_GRAPHS 256
#define HC 200
#define C_CH 100
#define SLOPE 0.2f

#define TM_TILES 3125          // 50000 / 16 (exact)
#define TN_TILES 25            // 200 / 8 (exact)
#define KS16_MAX 21            // 336 / 16
#define KSN 13                 // KS for K=200 layers
#define NB_SCAN 196            // ceil(50000/256)
#define AFRAG_N ((size_t)TM_TILES * KS16_MAX * 32)
// B scratch layer offsets (uint2 elements)
#define BOFF1 (TN_TILES * 21 * 32)                  // 16800
#define BLAYER (TN_TILES * KSN * 32)                // 10400
#define BTOT (BOFF1 + 4 * BLAYER)                   // 58400

// ---------------- scratch (device globals; no allocation allowed) ------------
__device__ float g_h[(size_t)N_NODES * HC];
__device__ float g_x[(size_t)N_NODES * HC];
__device__ float g_es[N_NODES * 2];
__device__ float g_ed[N_NODES * 2];
__device__ float g_alpha[(size_t)E_TOT * 2];
__device__ int   g_rowptr[N_NODES + 1];
__device__ int   g_cnt[N_NODES];
__device__ int   g_fill[N_NODES];
__device__ int   g_colsrc[E_TOT];
__device__ float g_pool[G_GRAPHS * HC];
__device__ int   g_bsum[256];
__device__ int   g_boff[256];
// A operand fragment planes (uint2): a01 = {a0(row r0), a1(row r1)}, a23 = {a2, a3}
__device__ uint2 g_a01h[AFRAG_N];
__device__ uint2 g_a23h[AFRAG_N];
__device__ uint2 g_a01l[AFRAG_N];
__device__ uint2 g_a23l[AFRAG_N];
// B operand fragments for all 5 layers
__device__ uint2 g_pbh[BTOT];
__device__ uint2 g_pbl[BTOT];

// ---------------- CSR build --------------------------------------------------
__global__ void k_init_counts() {
    int i = blockIdx.x * blockDim.x + threadIdx.x;
    if (i < N_NODES) { g_cnt[i] = 1; g_fill[i] = 1; }
}

__global__ void k_count(const int* __restrict__ ei) {
    int e = blockIdx.x * blockDim.x + threadIdx.x;
    if (e < N_EDGES) atomicAdd(&g_cnt[ei[N_EDGES + e]], 1);
}

__global__ void k_scan1() {
    __shared__ int ws[8];
    int b = blockIdx.x, t = threadIdx.x;
    int i = b * 256 + t;
    int lane = t & 31, w = t >> 5;
    int v = (i < N_NODES) ? g_cnt[i] : 0;
    int s = v;
#pragma unroll
    for (int off = 1; off < 32; off <<= 1) {
        int u = __shfl_up_sync(0xffffffffu, s, off);
        if (lane >= off) s += u;
    }
    if (lane == 31) ws[w] = s;
    __syncthreads();
    if (t == 0) {
        int run = 0;
#pragma unroll
        for (int j = 0; j < 8; j++) { int tmp = ws[j]; ws[j] = run; run += tmp; }
        g_bsum[b] = run;
    }
    __syncthreads();
    if (i < N_NODES) g_rowptr[i + 1] = s + ws[w];
}

__global__ void k_scan2() {
    __shared__ int ws[8];
    int t = threadIdx.x;
    int lane = t & 31, w = t >> 5;
    int v = (t < NB_SCAN) ? g_bsum[t] : 0;
    int s = v;
#pragma unroll
    for (int off = 1; off < 32; off <<= 1) {
        int u = __shfl_up_sync(0xffffffffu, s, off);
        if (lane >= off) s += u;
    }
    if (lane == 31) ws[w] = s;
    __syncthreads();
    if (t == 0) {
        int run = 0;
#pragma unroll
        for (int j = 0; j < 8; j++) { int tmp = ws[j]; ws[j] = run; run += tmp; }
    }
    __syncthreads();
    if (t < NB_SCAN) g_boff[t] = s + ws[w] - v;
}

// scan finalize + self-loop placement fused (rowptr[i] = rowptr[i+1]-cnt[i])
__global__ void k_scan3() {
    int i = blockIdx.x * blockDim.x + threadIdx.x;
    if (i < N_NODES) {
        int v = g_rowptr[i + 1] + g_boff[i >> 8];
        g_rowptr[i + 1] = v;
        g_colsrc[v - g_cnt[i]] = i;     // self-loop at slot 0 of each segment
        if (i == 0) g_rowptr[0] = 0;
    }
}

__global__ void k_fill(const int* __restrict__ ei) {
    int e = blockIdx.x * blockDim.x + threadIdx.x;
    if (e < N_EDGES) {
        int d = ei[N_EDGES + e];
        int pos = g_rowptr[d] + atomicAdd(&g_fill[d], 1);
        g_colsrc[pos] = ei[e];
    }
}

// ---------------- bf16 helpers -----------------------------------------------
__device__ __forceinline__ uint32_t packbf(float a, float b) {
    __nv_bfloat162 p = __floats2bfloat162_rn(a, b);
    return *(uint32_t*)&p;
}
__device__ __forceinline__ float bfhi(float v) {
    return __bfloat162float(__float2bfloat16_rn(v));
}

__device__ __forceinline__ void mma_bf16(float& c0, float& c1, float& c2, float& c3,
                                         uint32_t a0, uint32_t a1, uint32_t a2, uint32_t a3,
                                         uint32_t b0, uint32_t b1) {
    asm volatile(
        "mma.sync.aligned.m16n8k16.row.col.f32.bf16.bf16.f32 "
        "{%0,%1,%2,%3},{%4,%5,%6,%7},{%8,%9},{%0,%1,%2,%3};"
        : "+f"(c0), "+f"(c1), "+f"(c2), "+f"(c3)
        : "r"(a0), "r"(a1), "r"(a2), "r"(a3), "r"(b0), "r"(b1));
}

// ---------------- layer-0 A conversion (planar fragment layout) --------------
__global__ void k_convA0(const float* __restrict__ A, int K, int KS, int total) {
    int t = blockIdx.x * blockDim.x + threadIdx.x;
    if (t >= total) return;
    int lane = t & 31;
    int rest = t >> 5;
    int ks = rest % KS;
    int tm = rest / KS;
    int groupr = lane >> 2, kc = lane & 3;
    int r0 = tm * 16 + groupr, r1 = r0 + 8;
    int k0 = ks * 16 + kc * 2;
    float v[2][4];
    const float* p0 = A + (size_t)r0 * K;
    const float* p1 = A + (size_t)r1 * K;
#pragma unroll
    for (int j = 0; j < 4; j++) {
        int k = k0 + (j >> 1) * 8 + (j & 1);
        v[0][j] = (k < K) ? p0[k] : 0.f;
        v[1][j] = (k < K) ? p1[k] : 0.f;
    }
    float h[2][4], l[2][4];
#pragma unroll
    for (int r = 0; r < 2; r++)
#pragma unroll
        for (int j = 0; j < 4; j++) { h[r][j] = bfhi(v[r][j]); l[r][j] = v[r][j] - h[r][j]; }
    g_a01h[t] = make_uint2(packbf(h[0][0], h[0][1]), packbf(h[1][0], h[1][1]));
    g_a23h[t] = make_uint2(packbf(h[0][2], h[0][3]), packbf(h[1][2], h[1][3]));
    g_a01l[t] = make_uint2(packbf(l[0][0], l[0][1]), packbf(l[1][0], l[1][1]));
    g_a23l[t] = make_uint2(packbf(l[0][2], l[0][3]), packbf(l[1][2], l[1][3]));
}

// ---------------- all-layer B conversion in one launch -----------------------
__global__ void k_convB_all(const float* __restrict__ W0, const float* __restrict__ W1,
                            const float* __restrict__ W2, const float* __restrict__ W3,
                            const float* __restrict__ W4) {
    int t = blockIdx.x * blockDim.x + threadIdx.x;
    if (t >= BTOT) return;
    const float* B;
    int K, KS, lt;
    if (t < BOFF1) { B = W0; K = 336; KS = 21; lt = t; }
    else {
        int t2 = t - BOFF1;
        int L = t2 / BLAYER;
        lt = t2 % BLAYER;
        B = (L == 0) ? W1 : (L == 1) ? W2 : (L == 2) ? W3 : W4;
        K = 200; KS = KSN;
    }
    int lane = lt & 31;
    int rest = lt >> 5;
    int ks = rest % KS;
    int tn = rest / KS;
    int groupr = lane >> 2, kc = lane & 3;
    int n = tn * 8 + groupr;
    int k0 = ks * 16 + kc * 2;
    float v[4];
#pragma unroll
    for (int j = 0; j < 4; j++) {
        int k = k0 + (j >> 1) * 8 + (j & 1);
        v[j] = (k < K) ? B[(size_t)k * HC + n] : 0.f;
    }
    float h[4], l[4];
#pragma unroll
    for (int j = 0; j < 4; j++) { h[j] = bfhi(v[j]); l[j] = v[j] - h[j]; }
    g_pbh[t] = make_uint2(packbf(h[0], h[1]), packbf(h[2], h[3]));
    g_pbl[t] = make_uint2(packbf(l[0], l[1]), packbf(l[2], l[3]));
}

// ---------------- smem-free bf16x3 tensor-core GEMM (round-6 structure) ------
// block = 8 warps (4m x 2n), warp tile 32m x 32n -> 2x4 m16n8k16 tiles.
__global__ void __launch_bounds__(256)
k_gemm_tc(int KS, int Boff) {
    int tid = threadIdx.x;
    int lane = tid & 31, warp = tid >> 5;
    int wm = warp & 3, wn = warp >> 2;
    int tm0 = blockIdx.y * 8 + wm * 2;
    int tnB = blockIdx.x * 8 + wn * 4;
    if (tnB >= TN_TILES) return;

    bool mv0 = tm0 < TM_TILES;
    bool mv1 = (tm0 + 1) < TM_TILES;
    bool nv[4];
#pragma unroll
    for (int ni = 0; ni < 4; ni++) nv[ni] = (tnB + ni) < TN_TILES;

    size_t aBase0 = ((size_t)tm0 * KS) * 32 + lane;
    size_t aBase1 = aBase0 + (size_t)KS * 32;
    size_t bBase[4];
#pragma unroll
    for (int ni = 0; ni < 4; ni++)
        bBase[ni] = (size_t)Boff + ((size_t)(tnB + ni) * KS) * 32 + lane;

    float acc[2][4][4];
#pragma unroll
    for (int mi = 0; mi < 2; mi++)
#pragma unroll
        for (int ni = 0; ni < 4; ni++)
#pragma unroll
            for (int r = 0; r < 4; r++) acc[mi][ni][r] = 0.f;

    const uint2 z2 = make_uint2(0, 0);

#pragma unroll 2
    for (int ks = 0; ks < KS; ks++) {
        size_t off = (size_t)ks * 32;
        uint2 h01_0 = mv0 ? g_a01h[aBase0 + off] : z2;
        uint2 h23_0 = mv0 ? g_a23h[aBase0 + off] : z2;
        uint2 l01_0 = mv0 ? g_a01l[aBase0 + off] : z2;
        uint2 l23_0 = mv0 ? g_a23l[aBase0 + off] : z2;
        uint2 h01_1 = mv1 ? g_a01h[aBase1 + off] : z2;
        uint2 h23_1 = mv1 ? g_a23h[aBase1 + off] : z2;
        uint2 l01_1 = mv1 ? g_a01l[aBase1 + off] : z2;
        uint2 l23_1 = mv1 ? g_a23l[aBase1 + off] : z2;
        uint4 ah0 = make_uint4(h01_0.x, h01_0.y, h23_0.x, h23_0.y);
        uint4 al0 = make_uint4(l01_0.x, l01_0.y, l23_0.x, l23_0.y);
        uint4 ah1 = make_uint4(h01_1.x, h01_1.y, h23_1.x, h23_1.y);
        uint4 al1 = make_uint4(l01_1.x, l01_1.y, l23_1.x, l23_1.y);
        uint2 bh[4], bl[4];
#pragma unroll
        for (int ni = 0; ni < 4; ni++) {
            bh[ni] = nv[ni] ? g_pbh[bBase[ni] + off] : z2;
            bl[ni] = nv[ni] ? g_pbl[bBase[ni] + off] : z2;
        }
#pragma unroll
        for (int ni = 0; ni < 4; ni++) {
            {
                float* c = acc[0][ni];
                mma_bf16(c[0], c[1], c[2], c[3], ah0.x, ah0.y, ah0.z, ah0.w, bh[ni].x, bh[ni].y);
                mma_bf16(c[0], c[1], c[2], c[3], al0.x, al0.y, al0.z, al0.w, bh[ni].x, bh[ni].y);
                mma_bf16(c[0], c[1], c[2], c[3], ah0.x, ah0.y, ah0.z, ah0.w, bl[ni].x, bl[ni].y);
            }
            {
                float* c = acc[1][ni];
                mma_bf16(c[0], c[1], c[2], c[3], ah1.x, ah1.y, ah1.z, ah1.w, bh[ni].x, bh[ni].y);
                mma_bf16(c[0], c[1], c[2], c[3], al1.x, al1.y, al1.z, al1.w, bh[ni].x, bh[ni].y);
                mma_bf16(c[0], c[1], c[2], c[3], ah1.x, ah1.y, ah1.z, ah1.w, bl[ni].x, bl[ni].y);
            }
        }
    }

    int groupr = lane >> 2, kc = lane & 3;
#pragma unroll
    for (int mi = 0; mi < 2; mi++) {
        if (!(mi ? mv1 : mv0)) continue;
        int r = (tm0 + mi) * 16 + groupr;
#pragma unroll
        for (int ni = 0; ni < 4; ni++) {
            if (!nv[ni]) continue;
            int c = (tnB + ni) * 8 + kc * 2;
            g_h[(size_t)r * HC + c]           = acc[mi][ni][0];
            g_h[(size_t)r * HC + c + 1]       = acc[mi][ni][1];
            g_h[(size_t)(r + 8) * HC + c]     = acc[mi][ni][2];
            g_h[(size_t)(r + 8) * HC + c + 1] = acc[mi][ni][3];
        }
    }
}

// ---------------- per-node attention scores ----------------------------------
__global__ void k_scores(const float* __restrict__ a_s, const float* __restrict__ a_d) {
    int gwarp = (blockIdx.x * blockDim.x + threadIdx.x) >> 5;
    int lane = threadIdx.x & 31;
    if (gwarp >= N_NODES) return;
    const float* hr = g_h + (size_t)gwarp * HC;
    float s0s = 0.f, s1s = 0.f, s0d = 0.f, s1d = 0.f;
#pragma unroll
    for (int k = 0; k < 7; k++) {
        int c = lane + 32 * k;
        if (c < HC) {
            float v = hr[c];
            float vs = v * a_s[c], vd = v * a_d[c];
            if (c < C_CH) { s0s += vs; s0d += vd; }
            else          { s1s += vs; s1d += vd; }
        }
    }
#pragma unroll
    for (int off = 16; off; off >>= 1) {
        s0s += __shfl_xor_sync(0xffffffffu, s0s, off);
        s1s += __shfl_xor_sync(0xffffffffu, s1s, off);
        s0d += __shfl_xor_sync(0xffffffffu, s0d, off);
        s1d += __shfl_xor_sync(0xffffffffu, s1d, off);
    }
    if (lane == 0) {
        g_es[gwarp * 2 + 0] = s0s; g_es[gwarp * 2 + 1] = s1s;
        g_ed[gwarp * 2 + 0] = s0d; g_ed[gwarp * 2 + 1] = s1d;
    }
}

__device__ __forceinline__ float lrelu(float v) { return v >= 0.f ? v : SLOPE * v; }

// ---------------- warp-per-dst softmax + aggregate + bias + relu -------------
// writeFrag=1: output goes directly into next layer's A-operand fragment planes
// writeFrag=0 (last layer): output written to plain g_x for pooling.
__global__ void k_aggregate(const float* __restrict__ bias, int writeFrag) {
    __shared__ float sbuf[8][HC];
    int n = (blockIdx.x * blockDim.x + threadIdx.x) >> 5;
    int lane = threadIdx.x & 31;
    int w = (threadIdx.x >> 5);
    if (n >= N_NODES) return;
    int beg = g_rowptr[n], end = g_rowptr[n + 1];
    float ed0 = g_ed[n * 2 + 0], ed1 = g_ed[n * 2 + 1];

    float m0 = -1e30f, m1 = -1e30f;
    for (int i = beg + lane; i < end; i += 32) {
        int s = g_colsrc[i];
        m0 = fmaxf(m0, lrelu(g_es[s * 2 + 0] + ed0));
        m1 = fmaxf(m1, lrelu(g_es[s * 2 + 1] + ed1));
    }
#pragma unroll
    for (int off = 16; off; off >>= 1) {
        m0 = fmaxf(m0, __shfl_xor_sync(0xffffffffu, m0, off));
        m1 = fmaxf(m1, __shfl_xor_sync(0xffffffffu, m1, off));
    }

    float s0 = 0.f, s1 = 0.f;
    for (int i = beg + lane; i < end; i += 32) {
        int s = g_colsrc[i];
        float p0 = __expf(lrelu(g_es[s * 2 + 0] + ed0) - m0);
        float p1 = __expf(lrelu(g_es[s * 2 + 1] + ed1) - m1);
        ((float2*)g_alpha)[i] = make_float2(p0, p1);
        s0 += p0;
        s1 += p1;
    }
    __threadfence_block();
#pragma unroll
    for (int off = 16; off; off >>= 1) {
        s0 += __shfl_xor_sync(0xffffffffu, s0, off);
        s1 += __shfl_xor_sync(0xffffffffu, s1, off);
    }
    float inv0 = 1.f / (s0 + 1e-16f), inv1 = 1.f / (s1 + 1e-16f);

    float acc[7];
#pragma unroll
    for (int k = 0; k < 7; k++) acc[k] = 0.f;

    for (int i = beg; i < end; i++) {
        int s = g_colsrc[i];
        float2 p = ((const float2*)g_alpha)[i];
        float a0 = p.x * inv0;
        float a1 = p.y * inv1;
        const float* hr = g_h + (size_t)s * HC;
#pragma unroll
        for (int k = 0; k < 7; k++) {
            int c = lane + 32 * k;
            if (c < HC) acc[k] += (c < C_CH ? a0 : a1) * hr[c];
        }
    }

    if (!writeFrag) {
#pragma unroll
        for (int k = 0; k < 7; k++) {
            int c = lane + 32 * k;
            if (c < HC) {
                float v = acc[k] + bias[c];
                g_x[(size_t)n * HC + c] = v > 0.f ? v : 0.f;
            }
        }
        return;
    }

    // stage row to smem, then pack bf16 hi/lo fragment words for next layer
#pragma unroll
    for (int k = 0; k < 7; k++) {
        int c = lane + 32 * k;
        if (c < HC) {
            float v = acc[k] + bias[c];
            sbuf[w][c] = v > 0.f ? v : 0.f;
        }
    }
    __syncwarp();

    if (lane < 2 * KSN) {
        int ks = lane >> 1, ch = lane & 1;
        int base = ks * 16 + ch * 8;
        float f[8];
#pragma unroll
        for (int j = 0; j < 8; j++) f[j] = (base + j < HC) ? sbuf[w][base + j] : 0.f;
        uint32_t hw[4], lw[4];
#pragma unroll
        for (int kc = 0; kc < 4; kc++) {
            float a = f[2 * kc], b = f[2 * kc + 1];
            float ha = bfhi(a), hb = bfhi(b);
            hw[kc] = packbf(ha, hb);
            lw[kc] = packbf(a - ha, b - hb);
        }
        int tm = n >> 4, rr = n & 15;
        int comp = (rr < 8) ? 0 : 1;        // a0/a2 vs a1/a3 slot
        int groupr = rr & 7;
        size_t eidx = ((size_t)tm * KSN + ks) * 32 + groupr * 4;
        uint32_t* ph = (uint32_t*)(ch ? g_a23h : g_a01h);
        uint32_t* pl = (uint32_t*)(ch ? g_a23l : g_a01l);
#pragma unroll
        for (int kc = 0; kc < 4; kc++) {
            ph[(eidx + kc) * 2 + comp] = hw[kc];
            pl[(eidx + kc) * 2 + comp] = lw[kc];
        }
    }
}

// ---------------- global mean pool (batch sorted -> segment reduce) ----------
__global__ void k_pool_seg(const int* __restrict__ batch) {
    int g = blockIdx.x;
    int t = threadIdx.x;
    int lo = 0, hi = N_NODES;
    while (lo < hi) { int m = (lo + hi) >> 1; if (batch[m] < g) lo = m + 1; else hi = m; }
    int beg = lo;
    hi = N_NODES;
    while (lo < hi) { int m = (lo + hi) >> 1; if (batch[m] < g + 1) lo = m + 1; else hi = m; }
    int end = lo;
    float inv = 1.f / fmaxf((float)(end - beg), 1.f);
    for (int c = t; c < HC; c += blockDim.x) {
        float s = 0.f;
        for (int n = beg; n < end; n++) s += g_x[(size_t)n * HC + c];
        g_pool[g * HC + c] = s * inv;
    }
}

// ---------------- fused MLP head ---------------------------------------------
__global__ void k_mlp(const float* __restrict__ lw1, const float* __restrict__ lb1,
                      const float* __restrict__ lw2, const float* __restrict__ lb2,
                      const float* __restrict__ lw3, const float* __restrict__ lb3,
                      float* __restrict__ out) {
    int g = blockIdx.x;
    int t = threadIdx.x;
    __shared__ float buf[HC];
    __shared__ float t1[100];
    __shared__ float t2[100];
    for (int k = t; k < HC; k += blockDim.x) buf[k] = g_pool[g * HC + k];
    __syncthreads();
    if (t < 100) {
        float s = lb1[t];
        for (int k = 0; k < HC; k++) s += buf[k] * lw1[k * 100 + t];
        t1[t] = fmaxf(s, 0.f);
    }
    __syncthreads();
    if (t < 100) {
        float s = lb2[t];
        for (int k = 0; k < 100; k++) s += t1[k] * lw2[k * 100 + t];
        t2[t] = fmaxf(s, 0.f);
    }
    __syncthreads();
    if (t < 29) {
        float s = lb3[t];
        for (int k = 0; k < 100; k++) s += t2[k] * lw3[k * 29 + t];
        out[g * 29 + t] = s;
    }
}

// ---------------- launch ------------------------------------------------------
extern "C" void kernel_launch(void* const* d_in, const int* in_sizes, int n_in,
                              void* d_out, int out_size) {
    const float* x     = (const float*)d_in[0];
    const int*   ei    = (const int*)d_in[1];
    const int*   batch = (const int*)d_in[2];
    const float* W[5];
    const float* Asr[5];
    const float* Ads[5];
    const float* Bc[5];
    for (int i = 0; i < 5; i++) {
        W[i]   = (const float*)d_in[3 + 4 * i];
        Asr[i] = (const float*)d_in[4 + 4 * i];
        Ads[i] = (const float*)d_in[5 + 4 * i];
        Bc[i]  = (const float*)d_in[6 + 4 * i];
    }
    const float* lw1 = (const float*)d_in[23];
    const float* lb1 = (const float*)d_in[24];
    const float* lw2 = (const float*)d_in[25];
    const float* lb2 = (const float*)d_in[26];
    const float* lw3 = (const float*)d_in[27];
    const float* lb3 = (const float*)d_in[28];
    float* out = (float*)d_out;

    k_init_counts<<<(N_NODES + 255) / 256, 256>>>();
    k_count<<<(N_EDGES + 255) / 256, 256>>>(ei);
    k_scan1<<<NB_SCAN, 256>>>();
    k_scan2<<<1, 256>>>();
    k_scan3<<<(N_NODES + 255) / 256, 256>>>();
    k_fill<<<(N_EDGES + 255) / 256, 256>>>(ei);

    // operand conversion: layer-0 A from input x; all 5 layers' B in one shot
    {
        int totA = TM_TILES * 21 * 32;
        k_convA0<<<(totA + 255) / 256, 256>>>(x, 336, 21, totA);
        k_convB_all<<<(BTOT + 255) / 256, 256>>>(W[0], W[1], W[2], W[3], W[4]);
    }

    int KSs[5]  = {21, KSN, KSN, KSN, KSN};
    int Boffs[5] = {0, BOFF1, BOFF1 + BLAYER, BOFF1 + 2 * BLAYER, BOFF1 + 3 * BLAYER};
    int wblocks = (N_NODES + 7) / 8;
    dim3 gemmGrid(4, (TM_TILES + 7) / 8);

    for (int L = 0; L < 5; L++) {
        k_gemm_tc<<<gemmGrid, 256>>>(KSs[L], Boffs[L]);
        k_scores<<<wblocks, 256>>>(Asr[L], Ads[L]);
        k_aggregate<<<wblocks, 256>>>(Bc[L], (L < 4) ? 1 : 0);
    }
    k_pool_seg<<<G_GRAPHS, 256>>>(batch);
    k_mlp<<<G_GRAPHS, 128>>>(lw1, lb1, lw2, lb2, lw3, lb3, out);
}

// round 10
// speedup vs baseline: 1.8832x; 1.8832x over previous
#include <cuda_runtime.h>
#include <cuda_bf16.h>
#include <cstdint>

#define N_NODES 50000
#define N_EDGES 400000
#define E_TOT   (N_EDGES + N_NODES)
#define G_GRAPHS 256
#define HC 200
#define C_CH 100
#define SLOPE 0.2f

#define TM_TILES 3125          // 50000 / 16 (exact)
#define TN_TILES 25            // 200 / 8 (exact)
#define KS16_MAX 21            // 336 / 16
#define KSN 13                 // KS for K=200 layers
#define NB_SCAN 196            // ceil(50000/256)
// B scratch layer offsets (uint2 elements)
#define BOFF1 (TN_TILES * 21 * 32)                  // layer-0 region
#define BLAYER (TN_TILES * KSN * 32)
#define BTOT (BOFF1 + 4 * BLAYER)

// ---------------- scratch (device globals; no allocation allowed) ------------
__device__ float g_h[(size_t)N_NODES * HC];
__device__ float g_x[(size_t)N_NODES * HC];
__device__ float g_es[N_NODES * 2];
__device__ float g_ed[N_NODES * 2];
__device__ float g_alpha[(size_t)E_TOT * 2];
__device__ int   g_rowptr[N_NODES + 1];
__device__ int   g_cnt[N_NODES];
__device__ int   g_fill[N_NODES];
__device__ int   g_colsrc[E_TOT];
__device__ float g_pool[G_GRAPHS * HC];
__device__ int   g_bsum[256];
__device__ int   g_boff[256];
// permuted bf16 hi/lo operands in exact mma.m16n8k16 fragment order (round-6 layout)
__device__ uint4 g_pah[(size_t)TM_TILES * KS16_MAX * 32];
__device__ uint4 g_pal[(size_t)TM_TILES * KS16_MAX * 32];
__device__ uint2 g_pbh[BTOT];
__device__ uint2 g_pbl[BTOT];

// ---------------- CSR build --------------------------------------------------
__global__ void k_init_counts() {
    int i = blockIdx.x * blockDim.x + threadIdx.x;
    if (i < N_NODES) { g_cnt[i] = 1; g_fill[i] = 1; }
}

__global__ void k_count(const int* __restrict__ ei) {
    int e = blockIdx.x * blockDim.x + threadIdx.x;
    if (e < N_EDGES) atomicAdd(&g_cnt[ei[N_EDGES + e]], 1);
}

__global__ void k_scan1() {
    __shared__ int ws[8];
    int b = blockIdx.x, t = threadIdx.x;
    int i = b * 256 + t;
    int lane = t & 31, w = t >> 5;
    int v = (i < N_NODES) ? g_cnt[i] : 0;
    int s = v;
#pragma unroll
    for (int off = 1; off < 32; off <<= 1) {
        int u = __shfl_up_sync(0xffffffffu, s, off);
        if (lane >= off) s += u;
    }
    if (lane == 31) ws[w] = s;
    __syncthreads();
    if (t == 0) {
        int run = 0;
#pragma unroll
        for (int j = 0; j < 8; j++) { int tmp = ws[j]; ws[j] = run; run += tmp; }
        g_bsum[b] = run;
    }
    __syncthreads();
    if (i < N_NODES) g_rowptr[i + 1] = s + ws[w];
}

__global__ void k_scan2() {
    __shared__ int ws[8];
    int t = threadIdx.x;
    int lane = t & 31, w = t >> 5;
    int v = (t < NB_SCAN) ? g_bsum[t] : 0;
    int s = v;
#pragma unroll
    for (int off = 1; off < 32; off <<= 1) {
        int u = __shfl_up_sync(0xffffffffu, s, off);
        if (lane >= off) s += u;
    }
    if (lane == 31) ws[w] = s;
    __syncthreads();
    if (t == 0) {
        int run = 0;
#pragma unroll
        for (int j = 0; j < 8; j++) { int tmp = ws[j]; ws[j] = run; run += tmp; }
    }
    __syncthreads();
    if (t < NB_SCAN) g_boff[t] = s + ws[w] - v;
}

// scan finalize + self-loop placement fused (proven in rounds 8-9)
__global__ void k_scan3() {
    int i = blockIdx.x * blockDim.x + threadIdx.x;
    if (i < N_NODES) {
        int v = g_rowptr[i + 1] + g_boff[i >> 8];
        g_rowptr[i + 1] = v;
        g_colsrc[v - g_cnt[i]] = i;     // self-loop at slot 0 of each segment
        if (i == 0) g_rowptr[0] = 0;
    }
}

__global__ void k_fill(const int* __restrict__ ei) {
    int e = blockIdx.x * blockDim.x + threadIdx.x;
    if (e < N_EDGES) {
        int d = ei[N_EDGES + e];
        int pos = g_rowptr[d] + atomicAdd(&g_fill[d], 1);
        g_colsrc[pos] = ei[e];
    }
}

// ---------------- bf16 helpers -----------------------------------------------
__device__ __forceinline__ uint32_t packbf(float a, float b) {
    __nv_bfloat162 p = __floats2bfloat162_rn(a, b);
    return *(uint32_t*)&p;
}
__device__ __forceinline__ float bfhi(float v) {
    return __bfloat162float(__float2bfloat16_rn(v));
}

__device__ __forceinline__ void mma_bf16(float& c0, float& c1, float& c2, float& c3,
                                         uint32_t a0, uint32_t a1, uint32_t a2, uint32_t a3,
                                         uint32_t b0, uint32_t b1) {
    asm volatile(
        "mma.sync.aligned.m16n8k16.row.col.f32.bf16.bf16.f32 "
        "{%0,%1,%2,%3},{%4,%5,%6,%7},{%8,%9},{%0,%1,%2,%3};"
        : "+f"(c0), "+f"(c1), "+f"(c2), "+f"(c3)
        : "r"(a0), "r"(a1), "r"(a2), "r"(a3), "r"(b0), "r"(b1));
}

// ---------------- operand pre-permute + hi/lo bf16 split (round-6) -----------
__device__ __forceinline__ void convA_body(const float* __restrict__ A, int K, int KS, int t) {
    int lane = t & 31;
    int rest = t >> 5;
    int ks = rest % KS;
    int tm = rest / KS;
    int groupr = lane >> 2, kc = lane & 3;
    int r0 = tm * 16 + groupr, r1 = r0 + 8;
    int k0 = ks * 16 + kc * 2;
    float v[2][4];
    const float* p0 = A + (size_t)r0 * K;
    const float* p1 = A + (size_t)r1 * K;
#pragma unroll
    for (int j = 0; j < 4; j++) {
        int k = k0 + (j >> 1) * 8 + (j & 1);
        v[0][j] = (k < K) ? p0[k] : 0.f;
        v[1][j] = (k < K) ? p1[k] : 0.f;
    }
    float h[2][4], l[2][4];
#pragma unroll
    for (int r = 0; r < 2; r++)
#pragma unroll
        for (int j = 0; j < 4; j++) { h[r][j] = bfhi(v[r][j]); l[r][j] = v[r][j] - h[r][j]; }
    g_pah[t] = make_uint4(packbf(h[0][0], h[0][1]), packbf(h[1][0], h[1][1]),
                          packbf(h[0][2], h[0][3]), packbf(h[1][2], h[1][3]));
    g_pal[t] = make_uint4(packbf(l[0][0], l[0][1]), packbf(l[1][0], l[1][1]),
                          packbf(l[0][2], l[0][3]), packbf(l[1][2], l[1][3]));
}

__global__ void k_convA(const float* __restrict__ A, int K, int KS, int total) {
    int t = blockIdx.x * blockDim.x + threadIdx.x;
    if (t < total) convA_body(A, K, KS, t);
}
__global__ void k_convA_gx(int K, int KS, int total) {
    int t = blockIdx.x * blockDim.x + threadIdx.x;
    if (t < total) convA_body(g_x, K, KS, t);
}

// ---------------- all-layer B conversion in one launch (proven r8-r9) --------
__global__ void k_convB_all(const float* __restrict__ W0, const float* __restrict__ W1,
                            const float* __restrict__ W2, const float* __restrict__ W3,
                            const float* __restrict__ W4) {
    int t = blockIdx.x * blockDim.x + threadIdx.x;
    if (t >= BTOT) return;
    const float* B;
    int K, KS, lt;
    if (t < BOFF1) { B = W0; K = 336; KS = 21; lt = t; }
    else {
        int t2 = t - BOFF1;
        int L = t2 / BLAYER;
        lt = t2 % BLAYER;
        B = (L == 0) ? W1 : (L == 1) ? W2 : (L == 2) ? W3 : W4;
        K = 200; KS = KSN;
    }
    int lane = lt & 31;
    int rest = lt >> 5;
    int ks = rest % KS;
    int tn = rest / KS;
    int groupr = lane >> 2, kc = lane & 3;
    int n = tn * 8 + groupr;
    int k0 = ks * 16 + kc * 2;
    float v[4];
#pragma unroll
    for (int j = 0; j < 4; j++) {
        int k = k0 + (j >> 1) * 8 + (j & 1);
        v[j] = (k < K) ? B[(size_t)k * HC + n] : 0.f;
    }
    float h[4], l[4];
#pragma unroll
    for (int j = 0; j < 4; j++) { h[j] = bfhi(v[j]); l[j] = v[j] - h[j]; }
    g_pbh[t] = make_uint2(packbf(h[0], h[1]), packbf(h[2], h[3]));
    g_pbl[t] = make_uint2(packbf(l[0], l[1]), packbf(l[2], l[3]));
}

// ---------------- smem-free bf16x3 tensor-core GEMM --------------------------
// REGRID: 8 warps as 2m x 4n; block tile 64 rows x 128 cols; grid (2, 782).
// Same block count / registers / epilogue as round-6 — only A-reuse changes (4x -> 2x).
__global__ void __launch_bounds__(256)
k_gemm_tc(int KS, int Boff) {
    int tid = threadIdx.x;
    int lane = tid & 31, warp = tid >> 5;
    int wm = warp & 1, wn = warp >> 1;           // 2m x 4n
    int tm0 = blockIdx.y * 4 + wm * 2;
    int tnB = blockIdx.x * 16 + wn * 4;
    if (tnB >= TN_TILES) return;

    bool mv0 = tm0 < TM_TILES;
    bool mv1 = (tm0 + 1) < TM_TILES;
    bool nv[4];
#pragma unroll
    for (int ni = 0; ni < 4; ni++) nv[ni] = (tnB + ni) < TN_TILES;

    size_t aBase0 = ((size_t)tm0 * KS) * 32 + lane;
    size_t aBase1 = aBase0 + (size_t)KS * 32;
    size_t bBase[4];
#pragma unroll
    for (int ni = 0; ni < 4; ni++)
        bBase[ni] = (size_t)Boff + ((size_t)(tnB + ni) * KS) * 32 + lane;

    float acc[2][4][4];
#pragma unroll
    for (int mi = 0; mi < 2; mi++)
#pragma unroll
        for (int ni = 0; ni < 4; ni++)
#pragma unroll
            for (int r = 0; r < 4; r++) acc[mi][ni][r] = 0.f;

    const uint4 z4 = make_uint4(0, 0, 0, 0);
    const uint2 z2 = make_uint2(0, 0);

#pragma unroll 2
    for (int ks = 0; ks < KS; ks++) {
        size_t off = (size_t)ks * 32;
        uint4 ah0 = mv0 ? g_pah[aBase0 + off] : z4;
        uint4 al0 = mv0 ? g_pal[aBase0 + off] : z4;
        uint4 ah1 = mv1 ? g_pah[aBase1 + off] : z4;
        uint4 al1 = mv1 ? g_pal[aBase1 + off] : z4;
        uint2 bh[4], bl[4];
#pragma unroll
        for (int ni = 0; ni < 4; ni++) {
            bh[ni] = nv[ni] ? g_pbh[bBase[ni] + off] : z2;
            bl[ni] = nv[ni] ? g_pbl[bBase[ni] + off] : z2;
        }
#pragma unroll
        for (int ni = 0; ni < 4; ni++) {
            {
                float* c = acc[0][ni];
                mma_bf16(c[0], c[1], c[2], c[3], ah0.x, ah0.y, ah0.z, ah0.w, bh[ni].x, bh[ni].y);
                mma_bf16(c[0], c[1], c[2], c[3], al0.x, al0.y, al0.z, al0.w, bh[ni].x, bh[ni].y);
                mma_bf16(c[0], c[1], c[2], c[3], ah0.x, ah0.y, ah0.z, ah0.w, bl[ni].x, bl[ni].y);
            }
            {
                float* c = acc[1][ni];
                mma_bf16(c[0], c[1], c[2], c[3], ah1.x, ah1.y, ah1.z, ah1.w, bh[ni].x, bh[ni].y);
                mma_bf16(c[0], c[1], c[2], c[3], al1.x, al1.y, al1.z, al1.w, bh[ni].x, bh[ni].y);
                mma_bf16(c[0], c[1], c[2], c[3], ah1.x, ah1.y, ah1.z, ah1.w, bl[ni].x, bl[ni].y);
            }
        }
    }

    int groupr = lane >> 2, kc = lane & 3;
#pragma unroll
    for (int mi = 0; mi < 2; mi++) {
        if (!(mi ? mv1 : mv0)) continue;
        int r = (tm0 + mi) * 16 + groupr;
#pragma unroll
        for (int ni = 0; ni < 4; ni++) {
            if (!nv[ni]) continue;
            int c = (tnB + ni) * 8 + kc * 2;
            g_h[(size_t)r * HC + c]           = acc[mi][ni][0];
            g_h[(size_t)r * HC + c + 1]       = acc[mi][ni][1];
            g_h[(size_t)(r + 8) * HC + c]     = acc[mi][ni][2];
            g_h[(size_t)(r + 8) * HC + c + 1] = acc[mi][ni][3];
        }
    }
}

// ---------------- per-node attention scores ----------------------------------
__global__ void k_scores(const float* __restrict__ a_s, const float* __restrict__ a_d) {
    int gwarp = (blockIdx.x * blockDim.x + threadIdx.x) >> 5;
    int lane = threadIdx.x & 31;
    if (gwarp >= N_NODES) return;
    const float* hr = g_h + (size_t)gwarp * HC;
    float s0s = 0.f, s1s = 0.f, s0d = 0.f, s1d = 0.f;
#pragma unroll
    for (int k = 0; k < 7; k++) {
        int c = lane + 32 * k;
        if (c < HC) {
            float v = hr[c];
            float vs = v * a_s[c], vd = v * a_d[c];
            if (c < C_CH) { s0s += vs; s0d += vd; }
            else          { s1s += vs; s1d += vd; }
        }
    }
#pragma unroll
    for (int off = 16; off; off >>= 1) {
        s0s += __shfl_xor_sync(0xffffffffu, s0s, off);
        s1s += __shfl_xor_sync(0xffffffffu, s1s, off);
        s0d += __shfl_xor_sync(0xffffffffu, s0d, off);
        s1d += __shfl_xor_sync(0xffffffffu, s1d, off);
    }
    if (lane == 0) {
        g_es[gwarp * 2 + 0] = s0s; g_es[gwarp * 2 + 1] = s1s;
        g_ed[gwarp * 2 + 0] = s0d; g_ed[gwarp * 2 + 1] = s1d;
    }
}

__device__ __forceinline__ float lrelu(float v) { return v >= 0.f ? v : SLOPE * v; }

// ---------------- warp-per-dst softmax + aggregate + bias + relu -------------
__global__ void k_aggregate(const float* __restrict__ bias) {
    int n = (blockIdx.x * blockDim.x + threadIdx.x) >> 5;
    int lane = threadIdx.x & 31;
    if (n >= N_NODES) return;
    int beg = g_rowptr[n], end = g_rowptr[n + 1];
    float ed0 = g_ed[n * 2 + 0], ed1 = g_ed[n * 2 + 1];

    float m0 = -1e30f, m1 = -1e30f;
    for (int i = beg + lane; i < end; i += 32) {
        int s = g_colsrc[i];
        m0 = fmaxf(m0, lrelu(g_es[s * 2 + 0] + ed0));
        m1 = fmaxf(m1, lrelu(g_es[s * 2 + 1] + ed1));
    }
#pragma unroll
    for (int off = 16; off; off >>= 1) {
        m0 = fmaxf(m0, __shfl_xor_sync(0xffffffffu, m0, off));
        m1 = fmaxf(m1, __shfl_xor_sync(0xffffffffu, m1, off));
    }

    float s0 = 0.f, s1 = 0.f;
    for (int i = beg + lane; i < end; i += 32) {
        int s = g_colsrc[i];
        float p0 = __expf(lrelu(g_es[s * 2 + 0] + ed0) - m0);
        float p1 = __expf(lrelu(g_es[s * 2 + 1] + ed1) - m1);
        ((float2*)g_alpha)[i] = make_float2(p0, p1);
        s0 += p0;
        s1 += p1;
    }
    __threadfence_block();
#pragma unroll
    for (int off = 16; off; off >>= 1) {
        s0 += __shfl_xor_sync(0xffffffffu, s0, off);
        s1 += __shfl_xor_sync(0xffffffffu, s1, off);
    }
    float inv0 = 1.f / (s0 + 1e-16f), inv1 = 1.f / (s1 + 1e-16f);

    float acc[7];
#pragma unroll
    for (int k = 0; k < 7; k++) acc[k] = 0.f;

    for (int i = beg; i < end; i++) {
        int s = g_colsrc[i];
        float2 p = ((const float2*)g_alpha)[i];
        float a0 = p.x * inv0;
        float a1 = p.y * inv1;
        const float* hr = g_h + (size_t)s * HC;
#pragma unroll
        for (int k = 0; k < 7; k++) {
            int c = lane + 32 * k;
            if (c < HC) acc[k] += (c < C_CH ? a0 : a1) * hr[c];
        }
    }
#pragma unroll
    for (int k = 0; k < 7; k++) {
        int c = lane + 32 * k;
        if (c < HC) {
            float v = acc[k] + bias[c];
            g_x[(size_t)n * HC + c] = v > 0.f ? v : 0.f;
        }
    }
}

// ---------------- global mean pool (batch sorted -> segment reduce) ----------
__global__ void k_pool_seg(const int* __restrict__ batch) {
    int g = blockIdx.x;
    int t = threadIdx.x;
    int lo = 0, hi = N_NODES;
    while (lo < hi) { int m = (lo + hi) >> 1; if (batch[m] < g) lo = m + 1; else hi = m; }
    int beg = lo;
    hi = N_NODES;
    while (lo < hi) { int m = (lo + hi) >> 1; if (batch[m] < g + 1) lo = m + 1; else hi = m; }
    int end = lo;
    float inv = 1.f / fmaxf((float)(end - beg), 1.f);
    for (int c = t; c < HC; c += blockDim.x) {
        float s = 0.f;
        for (int n = beg; n < end; n++) s += g_x[(size_t)n * HC + c];
        g_pool[g * HC + c] = s * inv;
    }
}

// ---------------- fused MLP head ---------------------------------------------
__global__ void k_mlp(const float* __restrict__ lw1, const float* __restrict__ lb1,
                      const float* __restrict__ lw2, const float* __restrict__ lb2,
                      const float* __restrict__ lw3, const float* __restrict__ lb3,
                      float* __restrict__ out) {
    int g = blockIdx.x;
    int t = threadIdx.x;
    __shared__ float buf[HC];
    __shared__ float t1[100];
    __shared__ float t2[100];
    for (int k = t; k < HC; k += blockDim.x) buf[k] = g_pool[g * HC + k];
    __syncthreads();
    if (t < 100) {
        float s = lb1[t];
        for (int k = 0; k < HC; k++) s += buf[k] * lw1[k * 100 + t];
        t1[t] = fmaxf(s, 0.f);
    }
    __syncthreads();
    if (t < 100) {
        float s = lb2[t];
        for (int k = 0; k < 100; k++) s += t1[k] * lw2[k * 100 + t];
        t2[t] = fmaxf(s, 0.f);
    }
    __syncthreads();
    if (t < 29) {
        float s = lb3[t];
        for (int k = 0; k < 100; k++) s += t2[k] * lw3[k * 29 + t];
        out[g * 29 + t] = s;
    }
}

// ---------------- launch ------------------------------------------------------
extern "C" void kernel_launch(void* const* d_in, const int* in_sizes, int n_in,
                              void* d_out, int out_size) {
    const float* x     = (const float*)d_in[0];
    const int*   ei    = (const int*)d_in[1];
    const int*   batch = (const int*)d_in[2];
    const float* W[5];
    const float* Asr[5];
    const float* Ads[5];
    const float* Bc[5];
    for (int i = 0; i < 5; i++) {
        W[i]   = (const float*)d_in[3 + 4 * i];
        Asr[i] = (const float*)d_in[4 + 4 * i];
        Ads[i] = (const float*)d_in[5 + 4 * i];
        Bc[i]  = (const float*)d_in[6 + 4 * i];
    }
    const float* lw1 = (const float*)d_in[23];
    const float* lb1 = (const float*)d_in[24];
    const float* lw2 = (const float*)d_in[25];
    const float* lb2 = (const float*)d_in[26];
    const float* lw3 = (const float*)d_in[27];
    const float* lb3 = (const float*)d_in[28];
    float* out = (float*)d_out;

    k_init_counts<<<(N_NODES + 255) / 256, 256>>>();
    k_count<<<(N_EDGES + 255) / 256, 256>>>(ei);
    k_scan1<<<NB_SCAN, 256>>>();
    k_scan2<<<1, 256>>>();
    k_scan3<<<(N_NODES + 255) / 256, 256>>>();
    k_fill<<<(N_EDGES + 255) / 256, 256>>>(ei);
    k_convB_all<<<(BTOT + 255) / 256, 256>>>(W[0], W[1], W[2], W[3], W[4]);

    int KSs[5]   = {21, KSN, KSN, KSN, KSN};
    int Kd[5]    = {336, 200, 200, 200, 200};
    int Boffs[5] = {0, BOFF1, BOFF1 + BLAYER, BOFF1 + 2 * BLAYER, BOFF1 + 3 * BLAYER};
    int wblocks = (N_NODES + 7) / 8;
    dim3 gemmGrid(2, (TM_TILES + 3) / 4);

    for (int L = 0; L < 5; L++) {
        int KS = KSs[L];
        int totA = TM_TILES * KS * 32;
        if (L == 0) k_convA<<<(totA + 255) / 256, 256>>>(x, Kd[L], KS, totA);
        else        k_convA_gx<<<(totA + 255) / 256, 256>>>(Kd[L], KS, totA);
        k_gemm_tc<<<gemmGrid, 256>>>(KS, Boffs[L]);
        k_scores<<<wblocks, 256>>>(Asr[L], Ads[L]);
        k_aggregate<<<wblocks, 256>>>(Bc[L]);
    }
    k_pool_seg<<<G_GRAPHS, 256>>>(batch);
    k_mlp<<<G_GRAPHS, 128>>>(lw1, lb1, lw2, lb2, lw3, lb3, out);
}

// round 11
// speedup vs baseline: 2.0825x; 1.1058x over previous
#include <cuda_runtime.h>
#include <cuda_bf16.h>
#include <cstdint>

#define N_NODES 50000
#define N_EDGES 400000
#define E_TOT   (N_EDGES + N_NODES)
#define G_GRAPHS 256
#define HC 200
#define C_CH 100
#define SLOPE 0.2f

#define TM_TILES 3125          // 50000 / 16 (exact)
#define TN_TILES 25            // 200 / 8 (exact)
#define KSN 13                 // KS for K=200 layers
#define NB_SCAN 196            // ceil(50000/256)
// B scratch layer offsets (uint2 elements)
#define BOFF1 (TN_TILES * 21 * 32)                  // layer-0 region (K=336)
#define BLAYER (TN_TILES * KSN * 32)
#define BTOT (BOFF1 + 4 * BLAYER)

// ---------------- scratch (device globals; no allocation allowed) ------------
__device__ float g_h[(size_t)N_NODES * HC];
__device__ float g_x[(size_t)N_NODES * HC];
__device__ float g_es[N_NODES * 2];
__device__ float g_ed[N_NODES * 2];
__device__ float g_alpha[(size_t)E_TOT * 2];
__device__ int   g_rowptr[N_NODES + 1];
__device__ int   g_cnt[N_NODES];
__device__ int   g_fill[N_NODES];
__device__ int   g_colsrc[E_TOT];
__device__ float g_pool[G_GRAPHS * HC];
__device__ int   g_bsum[256];
__device__ int   g_boff[256];
// permuted bf16 hi/lo B operand in exact mma.m16n8k16 fragment order
__device__ uint2 g_pbh[BTOT];
__device__ uint2 g_pbl[BTOT];

// ---------------- CSR build --------------------------------------------------
__global__ void k_init_counts() {
    int i = blockIdx.x * blockDim.x + threadIdx.x;
    if (i < N_NODES) { g_cnt[i] = 1; g_fill[i] = 1; }
}

__global__ void k_count(const int* __restrict__ ei) {
    int e = blockIdx.x * blockDim.x + threadIdx.x;
    if (e < N_EDGES) atomicAdd(&g_cnt[ei[N_EDGES + e]], 1);
}

__global__ void k_scan1() {
    __shared__ int ws[8];
    int b = blockIdx.x, t = threadIdx.x;
    int i = b * 256 + t;
    int lane = t & 31, w = t >> 5;
    int v = (i < N_NODES) ? g_cnt[i] : 0;
    int s = v;
#pragma unroll
    for (int off = 1; off < 32; off <<= 1) {
        int u = __shfl_up_sync(0xffffffffu, s, off);
        if (lane >= off) s += u;
    }
    if (lane == 31) ws[w] = s;
    __syncthreads();
    if (t == 0) {
        int run = 0;
#pragma unroll
        for (int j = 0; j < 8; j++) { int tmp = ws[j]; ws[j] = run; run += tmp; }
        g_bsum[b] = run;
    }
    __syncthreads();
    if (i < N_NODES) g_rowptr[i + 1] = s + ws[w];
}

__global__ void k_scan2() {
    __shared__ int ws[8];
    int t = threadIdx.x;
    int lane = t & 31, w = t >> 5;
    int v = (t < NB_SCAN) ? g_bsum[t] : 0;
    int s = v;
#pragma unroll
    for (int off = 1; off < 32; off <<= 1) {
        int u = __shfl_up_sync(0xffffffffu, s, off);
        if (lane >= off) s += u;
    }
    if (lane == 31) ws[w] = s;
    __syncthreads();
    if (t == 0) {
        int run = 0;
#pragma unroll
        for (int j = 0; j < 8; j++) { int tmp = ws[j]; ws[j] = run; run += tmp; }
    }
    __syncthreads();
    if (t < NB_SCAN) g_boff[t] = s + ws[w] - v;
}

// scan finalize + self-loop placement fused (proven rounds 8-10)
__global__ void k_scan3() {
    int i = blockIdx.x * blockDim.x + threadIdx.x;
    if (i < N_NODES) {
        int v = g_rowptr[i + 1] + g_boff[i >> 8];
        g_rowptr[i + 1] = v;
        g_colsrc[v - g_cnt[i]] = i;     // self-loop at slot 0 of each segment
        if (i == 0) g_rowptr[0] = 0;
    }
}

__global__ void k_fill(const int* __restrict__ ei) {
    int e = blockIdx.x * blockDim.x + threadIdx.x;
    if (e < N_EDGES) {
        int d = ei[N_EDGES + e];
        int pos = g_rowptr[d] + atomicAdd(&g_fill[d], 1);
        g_colsrc[pos] = ei[e];
    }
}

// ---------------- bf16 helpers -----------------------------------------------
__device__ __forceinline__ uint32_t packbf(float a, float b) {
    __nv_bfloat162 p = __floats2bfloat162_rn(a, b);
    return *(uint32_t*)&p;
}
__device__ __forceinline__ float bfhi(float v) {
    return __bfloat162float(__float2bfloat16_rn(v));
}

__device__ __forceinline__ void mma_bf16(float& c0, float& c1, float& c2, float& c3,
                                         uint32_t a0, uint32_t a1, uint32_t a2, uint32_t a3,
                                         uint32_t b0, uint32_t b1) {
    asm volatile(
        "mma.sync.aligned.m16n8k16.row.col.f32.bf16.bf16.f32 "
        "{%0,%1,%2,%3},{%4,%5,%6,%7},{%8,%9},{%0,%1,%2,%3};"
        : "+f"(c0), "+f"(c1), "+f"(c2), "+f"(c3)
        : "r"(a0), "r"(a1), "r"(a2), "r"(a3), "r"(b0), "r"(b1));
}

// ---------------- all-layer B conversion in one launch (proven r8-r10) -------
__global__ void k_convB_all(const float* __restrict__ W0, const float* __restrict__ W1,
                            const float* __restrict__ W2, const float* __restrict__ W3,
                            const float* __restrict__ W4) {
    int t = blockIdx.x * blockDim.x + threadIdx.x;
    if (t >= BTOT) return;
    const float* B;
    int K, KS, lt;
    if (t < BOFF1) { B = W0; K = 336; KS = 21; lt = t; }
    else {
        int t2 = t - BOFF1;
        int L = t2 / BLAYER;
        lt = t2 % BLAYER;
        B = (L == 0) ? W1 : (L == 1) ? W2 : (L == 2) ? W3 : W4;
        K = 200; KS = KSN;
    }
    int lane = lt & 31;
    int rest = lt >> 5;
    int ks = rest % KS;
    int tn = rest / KS;
    int groupr = lane >> 2, kc = lane & 3;
    int n = tn * 8 + groupr;
    int k0 = ks * 16 + kc * 2;
    float v[4];
#pragma unroll
    for (int j = 0; j < 4; j++) {
        int k = k0 + (j >> 1) * 8 + (j & 1);
        v[j] = (k < K) ? B[(size_t)k * HC + n] : 0.f;
    }
    float h[4], l[4];
#pragma unroll
    for (int j = 0; j < 4; j++) { h[j] = bfhi(v[j]); l[j] = v[j] - h[j]; }
    g_pbh[t] = make_uint2(packbf(h[0], h[1]), packbf(h[2], h[3]));
    g_pbl[t] = make_uint2(packbf(l[0], l[1]), packbf(l[2], l[3]));
}

// ---------------- bf16x3 tensor-core GEMM, A converted in-register -----------
// Round-6 proven layout: 8 warps (4m x 2n), warp tile 32m x 32n, grid (4, 391).
// A is loaded DIRECTLY from fp32 row-major (g_x or external x) with per-lane
// LDG.64 fragment loads + in-register bf16 hi/lo split -> no convA pass.
__global__ void __launch_bounds__(256)
k_gemm_tc(const float* __restrict__ Aext, int useExt, int K, int KS, int Boff) {
    const float* A = useExt ? Aext : g_x;
    int tid = threadIdx.x;
    int lane = tid & 31, warp = tid >> 5;
    int wm = warp & 3, wn = warp >> 2;           // 4m x 2n
    int tm0 = blockIdx.y * 8 + wm * 2;
    int tnB = blockIdx.x * 8 + wn * 4;
    if (tnB >= TN_TILES) return;

    int groupr = lane >> 2, kc = lane & 3;
    bool mv0 = tm0 < TM_TILES;
    bool mv1 = (tm0 + 1) < TM_TILES;
    bool nv[4];
#pragma unroll
    for (int ni = 0; ni < 4; ni++) nv[ni] = (tnB + ni) < TN_TILES;

    // per-tile row pointers (rows are exact: N_NODES = TM_TILES*16)
    int r00 = tm0 * 16 + groupr;
    const float* pA0r0 = A + (size_t)(mv0 ? r00 : 0) * K;
    const float* pA0r1 = pA0r0 + (size_t)8 * K;
    const float* pA1r0 = A + (size_t)(mv1 ? (r00 + 16) : 0) * K;
    const float* pA1r1 = pA1r0 + (size_t)8 * K;

    size_t bBase[4];
#pragma unroll
    for (int ni = 0; ni < 4; ni++)
        bBase[ni] = (size_t)Boff + ((size_t)(tnB + ni) * KS) * 32 + lane;

    float acc[2][4][4];
#pragma unroll
    for (int mi = 0; mi < 2; mi++)
#pragma unroll
        for (int ni = 0; ni < 4; ni++)
#pragma unroll
            for (int r = 0; r < 4; r++) acc[mi][ni][r] = 0.f;

    const uint2 z2 = make_uint2(0, 0);
    const float2 zf = make_float2(0.f, 0.f);

#pragma unroll 2
    for (int ks = 0; ks < KS; ks++) {
        int k0 = ks * 16 + kc * 2;
        bool okL = (k0 < K);          // K even, k0 even -> k0+1 < K too
        bool okH = (k0 + 8 < K);
        bool m0L = mv0 && okL, m0H = mv0 && okH;
        bool m1L = mv1 && okL, m1H = mv1 && okH;

        // tile 0 fragments
        float2 v00 = m0L ? *(const float2*)(pA0r0 + k0)     : zf;   // a0
        float2 v01 = m0L ? *(const float2*)(pA0r1 + k0)     : zf;   // a1
        float2 v02 = m0H ? *(const float2*)(pA0r0 + k0 + 8) : zf;   // a2
        float2 v03 = m0H ? *(const float2*)(pA0r1 + k0 + 8) : zf;   // a3
        // tile 1 fragments
        float2 v10 = m1L ? *(const float2*)(pA1r0 + k0)     : zf;
        float2 v11 = m1L ? *(const float2*)(pA1r1 + k0)     : zf;
        float2 v12 = m1H ? *(const float2*)(pA1r0 + k0 + 8) : zf;
        float2 v13 = m1H ? *(const float2*)(pA1r1 + k0 + 8) : zf;

        float h;
        uint4 ah0, al0, ah1, al1;
        float hx, hy;
        hx = bfhi(v00.x); hy = bfhi(v00.y); ah0.x = packbf(hx, hy); al0.x = packbf(v00.x - hx, v00.y - hy);
        hx = bfhi(v01.x); hy = bfhi(v01.y); ah0.y = packbf(hx, hy); al0.y = packbf(v01.x - hx, v01.y - hy);
        hx = bfhi(v02.x); hy = bfhi(v02.y); ah0.z = packbf(hx, hy); al0.z = packbf(v02.x - hx, v02.y - hy);
        hx = bfhi(v03.x); hy = bfhi(v03.y); ah0.w = packbf(hx, hy); al0.w = packbf(v03.x - hx, v03.y - hy);
        hx = bfhi(v10.x); hy = bfhi(v10.y); ah1.x = packbf(hx, hy); al1.x = packbf(v10.x - hx, v10.y - hy);
        hx = bfhi(v11.x); hy = bfhi(v11.y); ah1.y = packbf(hx, hy); al1.y = packbf(v11.x - hx, v11.y - hy);
        hx = bfhi(v12.x); hy = bfhi(v12.y); ah1.z = packbf(hx, hy); al1.z = packbf(v12.x - hx, v12.y - hy);
        hx = bfhi(v13.x); hy = bfhi(v13.y); ah1.w = packbf(hx, hy); al1.w = packbf(v13.x - hx, v13.y - hy);
        (void)h;

        size_t off = (size_t)ks * 32;
        uint2 bh[4], bl[4];
#pragma unroll
        for (int ni = 0; ni < 4; ni++) {
            bh[ni] = nv[ni] ? g_pbh[bBase[ni] + off] : z2;
            bl[ni] = nv[ni] ? g_pbl[bBase[ni] + off] : z2;
        }
#pragma unroll
        for (int ni = 0; ni < 4; ni++) {
            {
                float* c = acc[0][ni];
                mma_bf16(c[0], c[1], c[2], c[3], ah0.x, ah0.y, ah0.z, ah0.w, bh[ni].x, bh[ni].y);
                mma_bf16(c[0], c[1], c[2], c[3], al0.x, al0.y, al0.z, al0.w, bh[ni].x, bh[ni].y);
                mma_bf16(c[0], c[1], c[2], c[3], ah0.x, ah0.y, ah0.z, ah0.w, bl[ni].x, bl[ni].y);
            }
            {
                float* c = acc[1][ni];
                mma_bf16(c[0], c[1], c[2], c[3], ah1.x, ah1.y, ah1.z, ah1.w, bh[ni].x, bh[ni].y);
                mma_bf16(c[0], c[1], c[2], c[3], al1.x, al1.y, al1.z, al1.w, bh[ni].x, bh[ni].y);
                mma_bf16(c[0], c[1], c[2], c[3], ah1.x, ah1.y, ah1.z, ah1.w, bl[ni].x, bl[ni].y);
            }
        }
    }

    // ---- epilogue (unchanged) ----
#pragma unroll
    for (int mi = 0; mi < 2; mi++) {
        if (!(mi ? mv1 : mv0)) continue;
        int r = (tm0 + mi) * 16 + groupr;
#pragma unroll
        for (int ni = 0; ni < 4; ni++) {
            if (!nv[ni]) continue;
            int c = (tnB + ni) * 8 + kc * 2;
            g_h[(size_t)r * HC + c]           = acc[mi][ni][0];
            g_h[(size_t)r * HC + c + 1]       = acc[mi][ni][1];
            g_h[(size_t)(r + 8) * HC + c]     = acc[mi][ni][2];
            g_h[(size_t)(r + 8) * HC + c + 1] = acc[mi][ni][3];
        }
    }
}

// ---------------- per-node attention scores ----------------------------------
__global__ void k_scores(const float* __restrict__ a_s, const float* __restrict__ a_d) {
    int gwarp = (blockIdx.x * blockDim.x + threadIdx.x) >> 5;
    int lane = threadIdx.x & 31;
    if (gwarp >= N_NODES) return;
    const float* hr = g_h + (size_t)gwarp * HC;
    float s0s = 0.f, s1s = 0.f, s0d = 0.f, s1d = 0.f;
#pragma unroll
    for (int k = 0; k < 7; k++) {
        int c = lane + 32 * k;
        if (c < HC) {
            float v = hr[c];
            float vs = v * a_s[c], vd = v * a_d[c];
            if (c < C_CH) { s0s += vs; s0d += vd; }
            else          { s1s += vs; s1d += vd; }
        }
    }
#pragma unroll
    for (int off = 16; off; off >>= 1) {
        s0s += __shfl_xor_sync(0xffffffffu, s0s, off);
        s1s += __shfl_xor_sync(0xffffffffu, s1s, off);
        s0d += __shfl_xor_sync(0xffffffffu, s0d, off);
        s1d += __shfl_xor_sync(0xffffffffu, s1d, off);
    }
    if (lane == 0) {
        g_es[gwarp * 2 + 0] = s0s; g_es[gwarp * 2 + 1] = s1s;
        g_ed[gwarp * 2 + 0] = s0d; g_ed[gwarp * 2 + 1] = s1d;
    }
}

__device__ __forceinline__ float lrelu(float v) { return v >= 0.f ? v : SLOPE * v; }

// ---------------- warp-per-dst softmax + aggregate + bias + relu -------------
__global__ void k_aggregate(const float* __restrict__ bias) {
    int n = (blockIdx.x * blockDim.x + threadIdx.x) >> 5;
    int lane = threadIdx.x & 31;
    if (n >= N_NODES) return;
    int beg = g_rowptr[n], end = g_rowptr[n + 1];
    float ed0 = g_ed[n * 2 + 0], ed1 = g_ed[n * 2 + 1];

    float m0 = -1e30f, m1 = -1e30f;
    for (int i = beg + lane; i < end; i += 32) {
        int s = g_colsrc[i];
        m0 = fmaxf(m0, lrelu(g_es[s * 2 + 0] + ed0));
        m1 = fmaxf(m1, lrelu(g_es[s * 2 + 1] + ed1));
    }
#pragma unroll
    for (int off = 16; off; off >>= 1) {
        m0 = fmaxf(m0, __shfl_xor_sync(0xffffffffu, m0, off));
        m1 = fmaxf(m1, __shfl_xor_sync(0xffffffffu, m1, off));
    }

    float s0 = 0.f, s1 = 0.f;
    for (int i = beg + lane; i < end; i += 32) {
        int s = g_colsrc[i];
        float p0 = __expf(lrelu(g_es[s * 2 + 0] + ed0) - m0);
        float p1 = __expf(lrelu(g_es[s * 2 + 1] + ed1) - m1);
        ((float2*)g_alpha)[i] = make_float2(p0, p1);
        s0 += p0;
        s1 += p1;
    }
    __threadfence_block();
#pragma unroll
    for (int off = 16; off; off >>= 1) {
        s0 += __shfl_xor_sync(0xffffffffu, s0, off);
        s1 += __shfl_xor_sync(0xffffffffu, s1, off);
    }
    float inv0 = 1.f / (s0 + 1e-16f), inv1 = 1.f / (s1 + 1e-16f);

    float acc[7];
#pragma unroll
    for (int k = 0; k < 7; k++) acc[k] = 0.f;

    for (int i = beg; i < end; i++) {
        int s = g_colsrc[i];
        float2 p = ((const float2*)g_alpha)[i];
        float a0 = p.x * inv0;
        float a1 = p.y * inv1;
        const float* hr = g_h + (size_t)s * HC;
#pragma unroll
        for (int k = 0; k < 7; k++) {
            int c = lane + 32 * k;
            if (c < HC) acc[k] += (c < C_CH ? a0 : a1) * hr[c];
        }
    }
#pragma unroll
    for (int k = 0; k < 7; k++) {
        int c = lane + 32 * k;
        if (c < HC) {
            float v = acc[k] + bias[c];
            g_x[(size_t)n * HC + c] = v > 0.f ? v : 0.f;
        }
    }
}

// ---------------- global mean pool (batch sorted -> segment reduce) ----------
__global__ void k_pool_seg(const int* __restrict__ batch) {
    int g = blockIdx.x;
    int t = threadIdx.x;
    int lo = 0, hi = N_NODES;
    while (lo < hi) { int m = (lo + hi) >> 1; if (batch[m] < g) lo = m + 1; else hi = m; }
    int beg = lo;
    hi = N_NODES;
    while (lo < hi) { int m = (lo + hi) >> 1; if (batch[m] < g + 1) lo = m + 1; else hi = m; }
    int end = lo;
    float inv = 1.f / fmaxf((float)(end - beg), 1.f);
    for (int c = t; c < HC; c += blockDim.x) {
        float s = 0.f;
        for (int n = beg; n < end; n++) s += g_x[(size_t)n * HC + c];
        g_pool[g * HC + c] = s * inv;
    }
}

// ---------------- fused MLP head ---------------------------------------------
__global__ void k_mlp(const float* __restrict__ lw1, const float* __restrict__ lb1,
                      const float* __restrict__ lw2, const float* __restrict__ lb2,
                      const float* __restrict__ lw3, const float* __restrict__ lb3,
                      float* __restrict__ out) {
    int g = blockIdx.x;
    int t = threadIdx.x;
    __shared__ float buf[HC];
    __shared__ float t1[100];
    __shared__ float t2[100];
    for (int k = t; k < HC; k += blockDim.x) buf[k] = g_pool[g * HC + k];
    __syncthreads();
    if (t < 100) {
        float s = lb1[t];
        for (int k = 0; k < HC; k++) s += buf[k] * lw1[k * 100 + t];
        t1[t] = fmaxf(s, 0.f);
    }
    __syncthreads();
    if (t < 100) {
        float s = lb2[t];
        for (int k = 0; k < 100; k++) s += t1[k] * lw2[k * 100 + t];
        t2[t] = fmaxf(s, 0.f);
    }
    __syncthreads();
    if (t < 29) {
        float s = lb3[t];
        for (int k = 0; k < 100; k++) s += t2[k] * lw3[k * 29 + t];
        out[g * 29 + t] = s;
    }
}

// ---------------- launch ------------------------------------------------------
extern "C" void kernel_launch(void* const* d_in, const int* in_sizes, int n_in,
                              void* d_out, int out_size) {
    const float* x     = (const float*)d_in[0];
    const int*   ei    = (const int*)d_in[1];
    const int*   batch = (const int*)d_in[2];
    const float* W[5];
    const float* Asr[5];
    const float* Ads[5];
    const float* Bc[5];
    for (int i = 0; i < 5; i++) {
        W[i]   = (const float*)d_in[3 + 4 * i];
        Asr[i] = (const float*)d_in[4 + 4 * i];
        Ads[i] = (const float*)d_in[5 + 4 * i];
        Bc[i]  = (const float*)d_in[6 + 4 * i];
    }
    const float* lw1 = (const float*)d_in[23];
    const float* lb1 = (const float*)d_in[24];
    const float* lw2 = (const float*)d_in[25];
    const float* lb2 = (const float*)d_in[26];
    const float* lw3 = (const float*)d_in[27];
    const float* lb3 = (const float*)d_in[28];
    float* out = (float*)d_out;

    k_init_counts<<<(N_NODES + 255) / 256, 256>>>();
    k_count<<<(N_EDGES + 255) / 256, 256>>>(ei);
    k_scan1<<<NB_SCAN, 256>>>();
    k_scan2<<<1, 256>>>();
    k_scan3<<<(N_NODES + 255) / 256, 256>>>();
    k_fill<<<(N_EDGES + 255) / 256, 256>>>(ei);
    k_convB_all<<<(BTOT + 255) / 256, 256>>>(W[0], W[1], W[2], W[3], W[4]);

    int KSs[5]   = {21, KSN, KSN, KSN, KSN};
    int Kd[5]    = {336, 200, 200, 200, 200};
    int Boffs[5] = {0, BOFF1, BOFF1 + BLAYER, BOFF1 + 2 * BLAYER, BOFF1 + 3 * BLAYER};
    int wblocks = (N_NODES + 7) / 8;
    dim3 gemmGrid(4, (TM_TILES + 7) / 8);   // round-6 proven layout

    for (int L = 0; L < 5; L++) {
        k_gemm_tc<<<gemmGrid, 256>>>(x, L == 0 ? 1 : 0, Kd[L], KSs[L], Boffs[L]);
        k_scores<<<wblocks, 256>>>(Asr[L], Ads[L]);
        k_aggregate<<<wblocks, 256>>>(Bc[L]);
    }
    k_pool_seg<<<G_GRAPHS, 256>>>(batch);
    k_mlp<<<G_GRAPHS, 128>>>(lw1, lb1, lw2, lb2, lw3, lb3, out);
}